// round 2
// baseline (speedup 1.0000x reference)
#include <cuda_runtime.h>
#include <math.h>
#include <stdint.h>

// Problem dims
#define B_   4
#define S_   4096
#define D_   1024
#define M_   16384          // B*S tokens
#define CH_  256            // scan chunk length
#define NCH_ 16             // S / CH

// ---------------- scratch (static __device__ arrays; no runtime alloc) ------
__device__ float g_omega[(size_t)M_ * D_];
__device__ float g_mag  [(size_t)M_ * D_];
__device__ float g_p1   [(size_t)M_ * D_];
__device__ float g_gate [(size_t)M_ * D_];
__device__ float g_phii [(size_t)M_ * D_];
__device__ float g_phi  [(size_t)M_ * D_];
__device__ float g_ctx  [(size_t)M_ * 4 * D_];
__device__ float g_h1   [(size_t)M_ * 2 * D_];
__device__ float g_gsum [B_ * NCH_ * D_];
__device__ float g_rsum [B_ * NCH_ * D_];
__device__ float g_isum [B_ * NCH_ * D_];
__device__ float g_msum [B_ * NCH_ * D_];

// ---------------- generic fp32 tiled GEMM: C = act(A@W + bias) (+ res) ------
// A: [M,K] row-major, W: [K,N] row-major, C: [M,N].
// act: 0=none, 1=gelu(exact), 2=sigmoid, 3=5*sigmoid
// Requires M%128==0, N%128==0, K%8==0 (true for all calls here).
__global__ __launch_bounds__(256, 2) void gemm_kernel(
    const float* __restrict__ A, const float* __restrict__ W,
    const float* __restrict__ bias, const float* __restrict__ res,
    float* __restrict__ C, int M, int K, int N, int act)
{
    __shared__ float As[8][128];
    __shared__ float Bs[8][128];

    const int tid = threadIdx.x;
    const int bM = blockIdx.y * 128;
    const int bN = blockIdx.x * 128;
    const int tx = tid & 15;        // 0..15  -> 8 cols each
    const int ty = tid >> 4;        // 0..15  -> 8 rows each

    // A-tile load mapping: 128 rows x 8 cols, one float4 per thread
    const int aRow = tid >> 1;             // 0..127
    const int aCol = (tid & 1) * 4;        // 0 or 4
    const float* Aptr = A + (size_t)(bM + aRow) * K + aCol;
    // B-tile load mapping: 8 rows x 128 cols, one float4 per thread
    const int bRow = tid >> 5;             // 0..7
    const int bCol = (tid & 31) * 4;       // 0..124
    const float* Wptr = W + (size_t)bRow * N + (bN + bCol);

    float acc[8][8];
#pragma unroll
    for (int i = 0; i < 8; i++)
#pragma unroll
        for (int j = 0; j < 8; j++) acc[i][j] = 0.f;

    for (int k0 = 0; k0 < K; k0 += 8) {
        float4 av = *reinterpret_cast<const float4*>(Aptr + k0);
        float4 bv = *reinterpret_cast<const float4*>(Wptr + (size_t)k0 * N);
        As[aCol + 0][aRow] = av.x;
        As[aCol + 1][aRow] = av.y;
        As[aCol + 2][aRow] = av.z;
        As[aCol + 3][aRow] = av.w;
        *reinterpret_cast<float4*>(&Bs[bRow][bCol]) = bv;
        __syncthreads();

#pragma unroll
        for (int kk = 0; kk < 8; kk++) {
            float a[8], b[8];
            *reinterpret_cast<float4*>(&a[0]) = *reinterpret_cast<const float4*>(&As[kk][ty * 8]);
            *reinterpret_cast<float4*>(&a[4]) = *reinterpret_cast<const float4*>(&As[kk][ty * 8 + 4]);
            *reinterpret_cast<float4*>(&b[0]) = *reinterpret_cast<const float4*>(&Bs[kk][tx * 8]);
            *reinterpret_cast<float4*>(&b[4]) = *reinterpret_cast<const float4*>(&Bs[kk][tx * 8 + 4]);
#pragma unroll
            for (int i = 0; i < 8; i++)
#pragma unroll
                for (int j = 0; j < 8; j++) acc[i][j] += a[i] * b[j];
        }
        __syncthreads();
    }

    // epilogue
#pragma unroll
    for (int i = 0; i < 8; i++) {
        const int r = bM + ty * 8 + i;
        const size_t rowoff = (size_t)r * N;
        float4 v4[2];
#pragma unroll
        for (int h = 0; h < 2; h++) {
            float* vv = reinterpret_cast<float*>(&v4[h]);
#pragma unroll
            for (int q = 0; q < 4; q++) {
                const int j = h * 4 + q;
                const int ccol = bN + tx * 8 + j;
                float v = acc[i][j] + bias[ccol];
                if (act == 1)      v = v * normcdff(v);
                else if (act == 2) v = 1.f / (1.f + expf(-v));
                else if (act == 3) v = 5.f / (1.f + expf(-v));
                if (res) v += res[rowoff + ccol];
                vv[q] = v;
            }
            *reinterpret_cast<float4*>(&C[rowoff + bN + tx * 8 + h * 4]) = v4[h];
        }
    }
}

// ---------------- scan phase 1: per-chunk sums of gated_omega ---------------
__global__ void chunk_gsum_kernel(const float* __restrict__ omega,
                                  const float* __restrict__ gate,
                                  const float* __restrict__ iscale,
                                  float* __restrict__ gsum)
{
    const int t = blockIdx.x * blockDim.x + threadIdx.x;   // B*NCH*D threads
    if (t >= B_ * NCH_ * D_) return;
    const int d = t % D_;
    const int c = (t / D_) % NCH_;
    const int b = t / (D_ * NCH_);
    const float sc = fabsf(iscale[d]);
    size_t idx = ((size_t)(b * S_ + c * CH_)) * D_ + d;
    float sum = 0.f;
    for (int s = 0; s < CH_; s++, idx += D_)
        sum += gate[idx] * omega[idx] * sc;
    gsum[(b * NCH_ + c) * D_ + d] = sum;
}

// exclusive scan over the 16 chunks, per (b,d), in place
__global__ void chunk_scan_kernel(float* __restrict__ v)
{
    const int t = blockIdx.x * blockDim.x + threadIdx.x;   // B*D threads
    if (t >= B_ * D_) return;
    const int d = t % D_;
    const int b = t / D_;
    float run = 0.f;
    for (int c = 0; c < NCH_; c++) {
        const int i = (b * NCH_ + c) * D_ + d;
        const float x = v[i];
        v[i] = run;
        run += x;
    }
}

// ---------------- scan phase 2: materialize phi, per-chunk memory sums ------
__global__ void phi_mem_kernel(const float* __restrict__ omega,
                               const float* __restrict__ gate,
                               const float* __restrict__ iscale,
                               const float* __restrict__ phii,
                               const float* __restrict__ mag,
                               const float* __restrict__ x,
                               const float* __restrict__ gsum,
                               float* __restrict__ phi,
                               float* __restrict__ rsum,
                               float* __restrict__ isum,
                               float* __restrict__ msum)
{
    const int t = blockIdx.x * blockDim.x + threadIdx.x;
    if (t >= B_ * NCH_ * D_) return;
    const int d = t % D_;
    const int c = (t / D_) % NCH_;
    const int b = t / (D_ * NCH_);
    const int co = (b * NCH_ + c) * D_ + d;
    const float sc = fabsf(iscale[d]);

    float run = gsum[co];
    float tR = 0.f, tI = 0.f, tM = 0.f;
    size_t idx = ((size_t)(b * S_ + c * CH_)) * D_ + d;
    for (int s = 0; s < CH_; s++, idx += D_) {
        run += gate[idx] * omega[idx] * sc;
        const float p = phii[idx] + run;
        phi[idx] = p;
        float sp, cp;
        sincosf(p, &sp, &cp);
        const float mg = mag[idx];
        const float wc = mg * x[idx];
        tR += wc * cp;
        tI += wc * sp;
        tM += mg;
    }
    rsum[co] = tR;
    isum[co] = tI;
    msum[co] = tM;
}

// ---------------- scan phase 3: replay with offsets, build context ----------
__global__ void ctx_kernel(const float* __restrict__ phi,
                           const float* __restrict__ mag,
                           const float* __restrict__ x,
                           const float* __restrict__ rsum,
                           const float* __restrict__ isum,
                           const float* __restrict__ msum,
                           float* __restrict__ ctx)
{
    const int t = blockIdx.x * blockDim.x + threadIdx.x;
    if (t >= B_ * NCH_ * D_) return;
    const int d = t % D_;
    const int c = (t / D_) % NCH_;
    const int b = t / (D_ * NCH_);
    const int co = (b * NCH_ + c) * D_ + d;

    float R = rsum[co], I = isum[co], Mg = msum[co];
    int tok = b * S_ + c * CH_;
    size_t idx = (size_t)tok * D_ + d;
    for (int s = 0; s < CH_; s++, idx += D_, tok++) {
        const float p = phi[idx];
        float sp, cp;
        sincosf(p, &sp, &cp);
        const float mg = mag[idx];
        const float xv = x[idx];
        const float wc = mg * xv;
        R += wc * cp;
        I += wc * sp;
        Mg += mg;
        const float inv = rsqrtf(Mg + 1e-8f);
        const float mr = R * inv;
        const float mi = I * inv;
        const size_t cb = (size_t)tok * (4 * D_);
        ctx[cb + d]            = xv * cp;
        ctx[cb + D_ + d]       = xv * sp;
        ctx[cb + 2 * D_ + d]   = mr * cp + mi * sp;
        ctx[cb + 3 * D_ + d]   = mi * cp - mr * sp;
    }
}

// ---------------- LayerNorm over last dim (4096), in place ------------------
__inline__ __device__ float warpSum(float v)
{
#pragma unroll
    for (int o = 16; o; o >>= 1) v += __shfl_xor_sync(0xffffffff, v, o);
    return v;
}

__global__ __launch_bounds__(256) void ln_kernel(float* __restrict__ ctx,
                                                 const float* __restrict__ gam,
                                                 const float* __restrict__ bet)
{
    const int tok = blockIdx.x;
    float* row = ctx + (size_t)tok * (4 * D_);
    float s = 0.f, s2 = 0.f;
    for (int i = threadIdx.x; i < 4 * D_; i += 256) {
        const float v = row[i];
        s += v;
        s2 += v * v;
    }
    s = warpSum(s);
    s2 = warpSum(s2);
    __shared__ float shs[8], shs2[8];
    const int wid = threadIdx.x >> 5, lane = threadIdx.x & 31;
    if (lane == 0) { shs[wid] = s; shs2[wid] = s2; }
    __syncthreads();
    s = 0.f; s2 = 0.f;
#pragma unroll
    for (int w = 0; w < 8; w++) { s += shs[w]; s2 += shs2[w]; }
    const float mu = s * (1.f / (4 * D_));
    const float var = s2 * (1.f / (4 * D_)) - mu * mu;
    const float inv = rsqrtf(var + 1e-5f);
    for (int i = threadIdx.x; i < 4 * D_; i += 256)
        row[i] = (row[i] - mu) * inv * gam[i] + bet[i];
}

// ---------------- launch ----------------------------------------------------
extern "C" void kernel_launch(void* const* d_in, const int* in_sizes, int n_in,
                              void* d_out, int out_size)
{
    const float* x       = (const float*)d_in[0];
    const float* w_omega = (const float*)d_in[1];
    const float* b_omega = (const float*)d_in[2];
    const float* w_p1    = (const float*)d_in[3];
    const float* b_p1    = (const float*)d_in[4];
    const float* w_p2    = (const float*)d_in[5];
    const float* b_p2    = (const float*)d_in[6];
    const float* w_gate  = (const float*)d_in[7];
    const float* b_gate  = (const float*)d_in[8];
    const float* iscale  = (const float*)d_in[9];
    const float* w_mag   = (const float*)d_in[10];
    const float* b_mag   = (const float*)d_in[11];
    const float* ln_g    = (const float*)d_in[12];
    const float* ln_b    = (const float*)d_in[13];
    const float* w_o1    = (const float*)d_in[14];
    const float* b_o1    = (const float*)d_in[15];
    const float* w_o2    = (const float*)d_in[16];
    const float* b_o2    = (const float*)d_in[17];
    float* out = (float*)d_out;

    float *p_omega, *p_mag, *p_p1, *p_gate, *p_phii, *p_phi, *p_ctx, *p_h1;
    float *p_gsum, *p_rsum, *p_isum, *p_msum;
    cudaGetSymbolAddress((void**)&p_omega, g_omega);
    cudaGetSymbolAddress((void**)&p_mag,   g_mag);
    cudaGetSymbolAddress((void**)&p_p1,    g_p1);
    cudaGetSymbolAddress((void**)&p_gate,  g_gate);
    cudaGetSymbolAddress((void**)&p_phii,  g_phii);
    cudaGetSymbolAddress((void**)&p_phi,   g_phi);
    cudaGetSymbolAddress((void**)&p_ctx,   g_ctx);
    cudaGetSymbolAddress((void**)&p_h1,    g_h1);
    cudaGetSymbolAddress((void**)&p_gsum,  g_gsum);
    cudaGetSymbolAddress((void**)&p_rsum,  g_rsum);
    cudaGetSymbolAddress((void**)&p_isum,  g_isum);
    cudaGetSymbolAddress((void**)&p_msum,  g_msum);

    const dim3 blk(256);

    // projections from x: [16384,1024] @ [1024,1024]
    {
        dim3 grid(D_ / 128, M_ / 128);
        gemm_kernel<<<grid, blk>>>(x, w_omega, b_omega, nullptr, p_omega, M_, D_, D_, 0);
        gemm_kernel<<<grid, blk>>>(x, w_mag,   b_mag,   nullptr, p_mag,   M_, D_, D_, 3);
        gemm_kernel<<<grid, blk>>>(x, w_p1,    b_p1,    nullptr, p_p1,    M_, D_, D_, 1);
        gemm_kernel<<<grid, blk>>>(x, w_gate,  b_gate,  nullptr, p_gate,  M_, D_, D_, 2);
        gemm_kernel<<<grid, blk>>>(p_p1, w_p2, b_p2,    nullptr, p_phii,  M_, D_, D_, 0);
    }

    // hierarchical scans
    const int nwork = B_ * NCH_ * D_;       // 65536
    chunk_gsum_kernel<<<nwork / 256, blk>>>(p_omega, p_gate, iscale, p_gsum);
    chunk_scan_kernel<<<(B_ * D_) / 256, blk>>>(p_gsum);
    phi_mem_kernel<<<nwork / 256, blk>>>(p_omega, p_gate, iscale, p_phii,
                                         p_mag, x, p_gsum, p_phi,
                                         p_rsum, p_isum, p_msum);
    chunk_scan_kernel<<<(B_ * D_) / 256, blk>>>(p_rsum);
    chunk_scan_kernel<<<(B_ * D_) / 256, blk>>>(p_isum);
    chunk_scan_kernel<<<(B_ * D_) / 256, blk>>>(p_msum);
    ctx_kernel<<<nwork / 256, blk>>>(p_phi, p_mag, x, p_rsum, p_isum, p_msum, p_ctx);

    // LayerNorm in place on context
    ln_kernel<<<M_, blk>>>(p_ctx, ln_g, ln_b);

    // output MLP
    {
        dim3 grid1((2 * D_) / 128, M_ / 128);
        gemm_kernel<<<grid1, blk>>>(p_ctx, w_o1, b_o1, nullptr, p_h1, M_, 4 * D_, 2 * D_, 1);
        dim3 grid2(D_ / 128, M_ / 128);
        gemm_kernel<<<grid2, blk>>>(p_h1, w_o2, b_o2, x, out, M_, 2 * D_, D_, 0);
    }
}

// round 4
// speedup vs baseline: 5.9376x; 5.9376x over previous
#include <cuda_runtime.h>
#include <cuda_fp16.h>
#include <math.h>
#include <stdint.h>

// Problem dims
#define B_   4
#define S_   4096
#define D_   1024
#define M_   16384
#define CH_  256
#define NCH_ 16

// ---------------- scratch ---------------------------------------------------
__device__ float g_omega[(size_t)M_ * D_];
__device__ float g_mag  [(size_t)M_ * D_];
__device__ float g_gate [(size_t)M_ * D_];
__device__ float g_phii [(size_t)M_ * D_];   // phi_init, then sin(phi)
__device__ float g_cos  [(size_t)M_ * D_];   // cos(phi)
__device__ float g_ctx  [(size_t)M_ * 4 * D_];
__device__ __half g_xh  [(size_t)M_ * D_];
__device__ __half g_p1h [(size_t)M_ * D_];
__device__ __half g_ctxh[(size_t)M_ * 4 * D_];
__device__ __half g_h1h [(size_t)M_ * 2 * D_];
__device__ __half g_wh  [5 * (size_t)D_ * D_];          // transposed [N,K] halves
__device__ __half g_wo1h[(size_t)(2 * D_) * (4 * D_)];
__device__ __half g_wo2h[(size_t)D_ * (2 * D_)];
__device__ float g_gsum [B_ * NCH_ * D_];
__device__ float g_rsum [B_ * NCH_ * D_];
__device__ float g_isum [B_ * NCH_ * D_];
__device__ float g_msum [B_ * NCH_ * D_];

// ---------------- PTX helpers (baseline ISA only: sm_80/75 features) --------
__device__ __forceinline__ uint32_t smem_u32(const void* p) {
    uint32_t a;
    asm("{ .reg .u64 t; cvta.to.shared.u64 t, %1; cvt.u32.u64 %0, t; }" : "=r"(a) : "l"(p));
    return a;
}

#define CP_ASYNC16(s, g) asm volatile("cp.async.cg.shared.global [%0], [%1], 16;" :: "r"(s), "l"(g) : "memory")
#define CP_COMMIT()      asm volatile("cp.async.commit_group;" ::: "memory")
#define CP_WAIT1()       asm volatile("cp.async.wait_group 1;" ::: "memory")

#define LDSM4(r0, r1, r2, r3, a)                                                \
    asm volatile("ldmatrix.sync.aligned.m8n8.x4.shared.b16 {%0,%1,%2,%3}, [%4];"\
        : "=r"(r0), "=r"(r1), "=r"(r2), "=r"(r3) : "r"(a))

#define MMA16816(d, a, b)                                                       \
    asm volatile("mma.sync.aligned.m16n8k16.row.col.f32.f16.f16.f32 "           \
        "{%0,%1,%2,%3}, {%4,%5,%6,%7}, {%8,%9}, {%0,%1,%2,%3};"                 \
        : "+f"((d)[0]), "+f"((d)[1]), "+f"((d)[2]), "+f"((d)[3])                \
        : "r"((a)[0]), "r"((a)[1]), "r"((a)[2]), "r"((a)[3]),                   \
          "r"((b)[0]), "r"((b)[1]))

// ---------------- fp16 tensor-core GEMM --------------------------------------
// C[M,N] = act(A[M,K] @ Bt[N,K]^T + bias) (+res)
// A, Bt: halves. Output: float to Cf, or half to Ch (if Ch != nullptr).
// CTA tile 128x128, K-stage 64. 8 warps (2 x 4), warp tile 64x32.
#define NSTAGE 3
#define STG_BYTES 32768
#define SMEM_GEMM (NSTAGE * STG_BYTES)

__global__ __launch_bounds__(256, 2) void mma_gemm(
    const __half* __restrict__ A, const __half* __restrict__ Bt,
    const float* __restrict__ bias, const float* __restrict__ res,
    float* __restrict__ Cf, __half* __restrict__ Ch,
    int K, int N, int act)
{
    extern __shared__ char smraw[];
    const uint32_t tileBase = smem_u32(smraw);
    const int tid = threadIdx.x;
    const int lane = tid & 31;
    const int wid = tid >> 5;
    const int warpM = wid & 1;      // 0..1 -> 64 rows
    const int warpN = wid >> 1;     // 0..3 -> 32 cols
    const int bM = blockIdx.y * 128;
    const int bN = blockIdx.x * 128;
    const int kIters = K >> 6;

    const __half* Ag = A + (size_t)bM * K;
    const __half* Bg = Bt + (size_t)bN * K;

    float acc[4][4][4];
#pragma unroll
    for (int i = 0; i < 4; i++)
#pragma unroll
        for (int j = 0; j < 4; j++)
#pragma unroll
            for (int e = 0; e < 4; e++) acc[i][j][e] = 0.f;

    // stage loader: A tile 128x64 half (16KB) + B tile 128x64 half (16KB)
    // smem row = 128B (8 chunks of 16B), chunk swizzle: c ^ (row & 7)
    auto load_stage = [&](int kt, int slot) {
        const uint32_t sA = tileBase + slot * STG_BYTES;
        const uint32_t sB = sA + 16384;
        const int k0 = kt << 6;
#pragma unroll
        for (int j = 0; j < 4; j++) {
            const int i = tid + (j << 8);
            const int row = i >> 3, c = i & 7;
            CP_ASYNC16(sA + row * 128 + (((c ^ (row & 7))) << 4),
                       Ag + (size_t)row * K + k0 + (c << 3));
        }
#pragma unroll
        for (int j = 0; j < 4; j++) {
            const int i = tid + (j << 8);
            const int row = i >> 3, c = i & 7;
            CP_ASYNC16(sB + row * 128 + (((c ^ (row & 7))) << 4),
                       Bg + (size_t)row * K + k0 + (c << 3));
        }
        CP_COMMIT();
    };

    load_stage(0, 0);
    load_stage(1, 1);

    for (int kt = 0; kt < kIters; kt++) {
        CP_WAIT1();
        __syncthreads();
        if (kt + 2 < kIters) load_stage(kt + 2, (kt + 2) % NSTAGE);

        const int slot = kt % NSTAGE;
        const uint32_t sA = tileBase + slot * STG_BYTES;
        const uint32_t sB = sA + 16384;

#pragma unroll
        for (int ks = 0; ks < 4; ks++) {
            const int c0 = ks * 2;
            uint32_t a[4][4], b[8];
#pragma unroll
            for (int mt = 0; mt < 4; mt++) {
                const int row = warpM * 64 + mt * 16 + (lane & 15);
                const int chunk = c0 + (lane >> 4);
                LDSM4(a[mt][0], a[mt][1], a[mt][2], a[mt][3],
                      sA + row * 128 + ((chunk ^ (row & 7)) << 4));
            }
#pragma unroll
            for (int bt = 0; bt < 2; bt++) {
                const int row = warpN * 32 + bt * 16 + (lane & 7) + ((lane & 16) >> 1);
                const int chunk = c0 + ((lane >> 3) & 1);
                LDSM4(b[bt * 4 + 0], b[bt * 4 + 1], b[bt * 4 + 2], b[bt * 4 + 3],
                      sB + row * 128 + ((chunk ^ (row & 7)) << 4));
            }
#pragma unroll
            for (int mt = 0; mt < 4; mt++)
#pragma unroll
                for (int nt = 0; nt < 4; nt++)
                    MMA16816(acc[mt][nt], a[mt], b + ((nt >> 1) * 4 + (nt & 1) * 2));
        }
    }

    // epilogue
    const int g = lane >> 2, q = lane & 3;
#pragma unroll
    for (int mt = 0; mt < 4; mt++) {
#pragma unroll
        for (int nt = 0; nt < 4; nt++) {
            const int col = bN + warpN * 32 + nt * 8 + q * 2;
            const float b0 = bias[col], b1 = bias[col + 1];
#pragma unroll
            for (int h = 0; h < 2; h++) {
                const int row = bM + warpM * 64 + mt * 16 + g + h * 8;
                float v0 = acc[mt][nt][h * 2 + 0] + b0;
                float v1 = acc[mt][nt][h * 2 + 1] + b1;
                if (act == 1)      { v0 = v0 * normcdff(v0); v1 = v1 * normcdff(v1); }
                else if (act == 2) { v0 = 1.f / (1.f + expf(-v0)); v1 = 1.f / (1.f + expf(-v1)); }
                else if (act == 3) { v0 = 5.f / (1.f + expf(-v0)); v1 = 5.f / (1.f + expf(-v1)); }
                if (res) {
                    v0 += res[(size_t)row * N + col];
                    v1 += res[(size_t)row * N + col + 1];
                }
                if (Ch) {
                    *reinterpret_cast<__half2*>(Ch + (size_t)row * N + col) =
                        __floats2half2_rn(v0, v1);
                } else {
                    *reinterpret_cast<float2*>(Cf + (size_t)row * N + col) =
                        make_float2(v0, v1);
                }
            }
        }
    }
}

// ---------------- prep kernels -----------------------------------------------
__global__ void f2h_kernel(const float* __restrict__ src,
                           __half* __restrict__ dst, int n)
{
    const int i = blockIdx.x * blockDim.x + threadIdx.x;
    if (i < n) dst[i] = __float2half_rn(src[i]);
}

// W[K,N] -> Wt[N,K] half
__global__ void transpose_h_kernel(const float* __restrict__ W,
                                   __half* __restrict__ Wt, int K, int N)
{
    __shared__ float t[32][33];
    const int k0 = blockIdx.y * 32, n0 = blockIdx.x * 32;
    t[threadIdx.y][threadIdx.x] = W[(size_t)(k0 + threadIdx.y) * N + n0 + threadIdx.x];
    __syncthreads();
    Wt[(size_t)(n0 + threadIdx.y) * K + k0 + threadIdx.x] =
        __float2half_rn(t[threadIdx.x][threadIdx.y]);
}

// ---------------- scan kernels ----------------------------------------------
__global__ void chunk_gsum_kernel(const float* __restrict__ omega,
                                  const float* __restrict__ gate,
                                  const float* __restrict__ iscale,
                                  float* __restrict__ gsum)
{
    const int t = blockIdx.x * blockDim.x + threadIdx.x;
    if (t >= B_ * NCH_ * D_) return;
    const int d = t % D_;
    const int c = (t / D_) % NCH_;
    const int b = t / (D_ * NCH_);
    const float sc = fabsf(iscale[d]);
    size_t idx = ((size_t)(b * S_ + c * CH_)) * D_ + d;
    float sum = 0.f;
    for (int s = 0; s < CH_; s++, idx += D_)
        sum += gate[idx] * omega[idx] * sc;
    gsum[(b * NCH_ + c) * D_ + d] = sum;
}

__global__ void chunk_scan_kernel(float* __restrict__ v)
{
    const int t = blockIdx.x * blockDim.x + threadIdx.x;
    if (t >= B_ * D_) return;
    const int d = t % D_;
    const int b = t / D_;
    float run = 0.f;
    for (int c = 0; c < NCH_; c++) {
        const int i = (b * NCH_ + c) * D_ + d;
        const float x = v[i];
        v[i] = run;
        run += x;
    }
}

__global__ void phi_mem_kernel(const float* __restrict__ omega,
                               const float* __restrict__ gate,
                               const float* __restrict__ iscale,
                               float* __restrict__ phii,   // in: phi_init, out: sin(phi)
                               const float* __restrict__ mag,
                               const float* __restrict__ x,
                               const float* __restrict__ gsum,
                               float* __restrict__ cosphi,
                               float* __restrict__ rsum,
                               float* __restrict__ isum,
                               float* __restrict__ msum)
{
    const int t = blockIdx.x * blockDim.x + threadIdx.x;
    if (t >= B_ * NCH_ * D_) return;
    const int d = t % D_;
    const int c = (t / D_) % NCH_;
    const int b = t / (D_ * NCH_);
    const int co = (b * NCH_ + c) * D_ + d;
    const float sc = fabsf(iscale[d]);

    float run = gsum[co];
    float tR = 0.f, tI = 0.f, tM = 0.f;
    size_t idx = ((size_t)(b * S_ + c * CH_)) * D_ + d;
    for (int s = 0; s < CH_; s++, idx += D_) {
        run += gate[idx] * omega[idx] * sc;
        const float p = phii[idx] + run;
        float sp, cp;
        sincosf(p, &sp, &cp);
        cosphi[idx] = cp;
        phii[idx] = sp;
        const float mg = mag[idx];
        const float wc = mg * x[idx];
        tR += wc * cp;
        tI += wc * sp;
        tM += mg;
    }
    rsum[co] = tR;
    isum[co] = tI;
    msum[co] = tM;
}

__global__ void ctx_kernel(const float* __restrict__ cosphi,
                           const float* __restrict__ sinphi,
                           const float* __restrict__ mag,
                           const float* __restrict__ x,
                           const float* __restrict__ rsum,
                           const float* __restrict__ isum,
                           const float* __restrict__ msum,
                           float* __restrict__ ctx)
{
    const int t = blockIdx.x * blockDim.x + threadIdx.x;
    if (t >= B_ * NCH_ * D_) return;
    const int d = t % D_;
    const int c = (t / D_) % NCH_;
    const int b = t / (D_ * NCH_);
    const int co = (b * NCH_ + c) * D_ + d;

    float R = rsum[co], I = isum[co], Mg = msum[co];
    int tok = b * S_ + c * CH_;
    size_t idx = (size_t)tok * D_ + d;
    for (int s = 0; s < CH_; s++, idx += D_, tok++) {
        const float cp = cosphi[idx];
        const float sp = sinphi[idx];
        const float mg = mag[idx];
        const float xv = x[idx];
        const float wc = mg * xv;
        R += wc * cp;
        I += wc * sp;
        Mg += mg;
        const float inv = rsqrtf(Mg + 1e-8f);
        const float mr = R * inv;
        const float mi = I * inv;
        const size_t cb = (size_t)tok * (4 * D_);
        ctx[cb + d]          = xv * cp;
        ctx[cb + D_ + d]     = xv * sp;
        ctx[cb + 2 * D_ + d] = mr * cp + mi * sp;
        ctx[cb + 3 * D_ + d] = mi * cp - mr * sp;
    }
}

// ---------------- LayerNorm -> half ------------------------------------------
__inline__ __device__ float warpSum(float v)
{
#pragma unroll
    for (int o = 16; o; o >>= 1) v += __shfl_xor_sync(0xffffffff, v, o);
    return v;
}

__global__ __launch_bounds__(256) void ln_kernel(const float* __restrict__ ctx,
                                                 const float* __restrict__ gam,
                                                 const float* __restrict__ bet,
                                                 __half* __restrict__ outh)
{
    const int tok = blockIdx.x;
    const float* row = ctx + (size_t)tok * (4 * D_);
    __half* orow = outh + (size_t)tok * (4 * D_);
    float s = 0.f, s2 = 0.f;
    for (int i = threadIdx.x; i < 4 * D_; i += 256) {
        const float v = row[i];
        s += v;
        s2 += v * v;
    }
    s = warpSum(s);
    s2 = warpSum(s2);
    __shared__ float shs[8], shs2[8];
    const int wid = threadIdx.x >> 5, lane = threadIdx.x & 31;
    if (lane == 0) { shs[wid] = s; shs2[wid] = s2; }
    __syncthreads();
    s = 0.f; s2 = 0.f;
#pragma unroll
    for (int w = 0; w < 8; w++) { s += shs[w]; s2 += shs2[w]; }
    const float mu = s * (1.f / (4 * D_));
    const float var = s2 * (1.f / (4 * D_)) - mu * mu;
    const float inv = rsqrtf(var + 1e-5f);
    for (int i = threadIdx.x; i < 4 * D_; i += 256)
        orow[i] = __float2half_rn((row[i] - mu) * inv * gam[i] + bet[i]);
}

// ---------------- launch ----------------------------------------------------
extern "C" void kernel_launch(void* const* d_in, const int* in_sizes, int n_in,
                              void* d_out, int out_size)
{
    const float* x       = (const float*)d_in[0];
    const float* w_omega = (const float*)d_in[1];
    const float* b_omega = (const float*)d_in[2];
    const float* w_p1    = (const float*)d_in[3];
    const float* b_p1    = (const float*)d_in[4];
    const float* w_p2    = (const float*)d_in[5];
    const float* b_p2    = (const float*)d_in[6];
    const float* w_gate  = (const float*)d_in[7];
    const float* b_gate  = (const float*)d_in[8];
    const float* iscale  = (const float*)d_in[9];
    const float* w_mag   = (const float*)d_in[10];
    const float* b_mag   = (const float*)d_in[11];
    const float* ln_g    = (const float*)d_in[12];
    const float* ln_b    = (const float*)d_in[13];
    const float* w_o1    = (const float*)d_in[14];
    const float* b_o1    = (const float*)d_in[15];
    const float* w_o2    = (const float*)d_in[16];
    const float* b_o2    = (const float*)d_in[17];
    float* out = (float*)d_out;

    float *p_omega, *p_mag, *p_gate, *p_phii, *p_cos, *p_ctx;
    float *p_gsum, *p_rsum, *p_isum, *p_msum;
    __half *p_xh, *p_p1h, *p_ctxh, *p_h1h, *p_wh, *p_wo1h, *p_wo2h;
    cudaGetSymbolAddress((void**)&p_omega, g_omega);
    cudaGetSymbolAddress((void**)&p_mag,   g_mag);
    cudaGetSymbolAddress((void**)&p_gate,  g_gate);
    cudaGetSymbolAddress((void**)&p_phii,  g_phii);
    cudaGetSymbolAddress((void**)&p_cos,   g_cos);
    cudaGetSymbolAddress((void**)&p_ctx,   g_ctx);
    cudaGetSymbolAddress((void**)&p_xh,    g_xh);
    cudaGetSymbolAddress((void**)&p_p1h,   g_p1h);
    cudaGetSymbolAddress((void**)&p_ctxh,  g_ctxh);
    cudaGetSymbolAddress((void**)&p_h1h,   g_h1h);
    cudaGetSymbolAddress((void**)&p_wh,    g_wh);
    cudaGetSymbolAddress((void**)&p_wo1h,  g_wo1h);
    cudaGetSymbolAddress((void**)&p_wo2h,  g_wo2h);
    cudaGetSymbolAddress((void**)&p_gsum,  g_gsum);
    cudaGetSymbolAddress((void**)&p_rsum,  g_rsum);
    cudaGetSymbolAddress((void**)&p_isum,  g_isum);
    cudaGetSymbolAddress((void**)&p_msum,  g_msum);

    static bool attr_set = false;
    if (!attr_set) {
        cudaFuncSetAttribute(mma_gemm, cudaFuncAttributeMaxDynamicSharedMemorySize, SMEM_GEMM);
        attr_set = true;
    }

    const dim3 blk(256);

    // --- prep: fp16 conversion of activations/weights ---
    f2h_kernel<<<(M_ * D_) / 256, blk>>>(x, p_xh, M_ * D_);
    {
        dim3 tb(32, 32);
        dim3 gD(D_ / 32, D_ / 32);
        transpose_h_kernel<<<gD, tb>>>(w_omega, p_wh + 0 * (size_t)D_ * D_, D_, D_);
        transpose_h_kernel<<<gD, tb>>>(w_mag,   p_wh + 1 * (size_t)D_ * D_, D_, D_);
        transpose_h_kernel<<<gD, tb>>>(w_p1,    p_wh + 2 * (size_t)D_ * D_, D_, D_);
        transpose_h_kernel<<<gD, tb>>>(w_gate,  p_wh + 3 * (size_t)D_ * D_, D_, D_);
        transpose_h_kernel<<<gD, tb>>>(w_p2,    p_wh + 4 * (size_t)D_ * D_, D_, D_);
        transpose_h_kernel<<<dim3((2 * D_) / 32, (4 * D_) / 32), tb>>>(w_o1, p_wo1h, 4 * D_, 2 * D_);
        transpose_h_kernel<<<dim3(D_ / 32, (2 * D_) / 32), tb>>>(w_o2, p_wo2h, 2 * D_, D_);
    }

    // --- projection GEMMs, CTA tile 128x128 ---
    {
        dim3 g(D_ / 128, M_ / 128);
        mma_gemm<<<g, blk, SMEM_GEMM>>>(p_xh, p_wh + 0 * (size_t)D_ * D_, b_omega, nullptr, p_omega, nullptr, D_, D_, 0);
        mma_gemm<<<g, blk, SMEM_GEMM>>>(p_xh, p_wh + 1 * (size_t)D_ * D_, b_mag,   nullptr, p_mag,   nullptr, D_, D_, 3);
        mma_gemm<<<g, blk, SMEM_GEMM>>>(p_xh, p_wh + 2 * (size_t)D_ * D_, b_p1,    nullptr, nullptr, p_p1h,   D_, D_, 1);
        mma_gemm<<<g, blk, SMEM_GEMM>>>(p_xh, p_wh + 3 * (size_t)D_ * D_, b_gate,  nullptr, p_gate,  nullptr, D_, D_, 2);
        mma_gemm<<<g, blk, SMEM_GEMM>>>(p_p1h, p_wh + 4 * (size_t)D_ * D_, b_p2,   nullptr, p_phii,  nullptr, D_, D_, 0);
    }

    // --- hierarchical scans ---
    const int nwork = B_ * NCH_ * D_;
    chunk_gsum_kernel<<<nwork / 256, blk>>>(p_omega, p_gate, iscale, p_gsum);
    chunk_scan_kernel<<<(B_ * D_) / 256, blk>>>(p_gsum);
    phi_mem_kernel<<<nwork / 256, blk>>>(p_omega, p_gate, iscale, p_phii,
                                         p_mag, x, p_gsum, p_cos,
                                         p_rsum, p_isum, p_msum);
    chunk_scan_kernel<<<(B_ * D_) / 256, blk>>>(p_rsum);
    chunk_scan_kernel<<<(B_ * D_) / 256, blk>>>(p_isum);
    chunk_scan_kernel<<<(B_ * D_) / 256, blk>>>(p_msum);
    ctx_kernel<<<nwork / 256, blk>>>(p_cos, p_phii, p_mag, x, p_rsum, p_isum, p_msum, p_ctx);

    // --- LayerNorm -> half ---
    ln_kernel<<<M_, blk>>>(p_ctx, ln_g, ln_b, p_ctxh);

    // --- output MLP ---
    {
        dim3 g1((2 * D_) / 128, M_ / 128);
        mma_gemm<<<g1, blk, SMEM_GEMM>>>(p_ctxh, p_wo1h, b_o1, nullptr, nullptr, p_h1h, 4 * D_, 2 * D_, 1);
        dim3 g2(D_ / 128, M_ / 128);
        mma_gemm<<<g2, blk, SMEM_GEMM>>>(p_h1h, p_wo2h, b_o2, x, out, nullptr, 2 * D_, D_, 0);
    }
}